// round 10
// baseline (speedup 1.0000x reference)
#include <cuda_runtime.h>

// SPD log-map: for each 64x64 SPD matrix A, compute logm(A) = U diag(log w) U^T
// and emit the row-major upper triangle (2080 floats).
//
// One-sided Jacobi on B := A; at convergence columns are orthogonal with
// norms = eigenvalues, and logm(A) = B diag(log(l)/l^2) B^T.
//  - 256 threads/CTA, 8 CTAs/SM; each 8-lane GROUP owns one column pair
//    (4 pairs per warp -> amortizes shfl/math/barrier/index cost)
//  - float2 column layout, stride 40 float2 (80 floats, mod 32 = 16 ->
//    4 groups of consecutive columns tile the banks in 2 phases = minimum)
//  - 3-shfl butterfly reduction within 8-lane groups
//  - cached column norms updated analytically per rotation
//  - incremental round-robin index bookkeeping

#define MDIM 64
#define LD2  40          // float2 stride per column
#define LDF  80          // same stride in floats
#define MAXSWEEP 24
#define NTRI 2080
#define RTOL 1e-13f      // rotate above ~3e-7 relative orthogonality
#define QTOL 1e-8f       // sweep "significant" above ~1e-4 relative

__device__ __forceinline__ float grp_sum(float v) {
    #pragma unroll
    for (int o = 4; o; o >>= 1)
        v += __shfl_xor_sync(0xffffffffu, v, o);
    return v;                 // sum within each 8-lane group
}

__global__ __launch_bounds__(256, 8)
void spd_log_kernel(const float* __restrict__ in, float* __restrict__ out)
{
    __shared__ float2 Bs[MDIM * LD2];   // column c: float2 j = rows (2j,2j+1)
    __shared__ float  cn[MDIM];
    __shared__ float  dv[MDIM];
    __shared__ int    nsig;

    const int tid    = threadIdx.x;
    const int pairid = tid >> 3;        // 0..31: 8-lane group id
    const int gl     = tid & 7;         // lane within group
    const int warp   = tid >> 5;        // 0..7
    const int lane   = tid & 31;

    float* Bf = (float*)Bs;             // B[r, c] == Bf[c*LDF + r]

    const float* A = in  + (size_t)blockIdx.x * (MDIM * MDIM);
    float*       O = out + (size_t)blockIdx.x * NTRI;

    // Load (A symmetric): Bf[c*LDF + r] = A[c*64 + r]; contiguous both sides.
    for (int e = tid; e < MDIM * MDIM; e += 256) {
        int c = e >> 6, r = e & 63;
        Bf[c * LDF + r] = A[e];
    }
    if (tid == 0) nsig = 0;
    __syncthreads();

    // ---- One-sided Jacobi sweeps (adaptive) ----
    for (int sw = 0; sw < MAXSWEEP; sw++) {
        // Exact column norms at sweep start: group g -> cols g, g+32.
        #pragma unroll
        for (int h = 0; h < 2; h++) {
            int k = pairid + 32 * h;
            const float2* col = Bs + k * LD2;
            float2 x0 = col[gl],      x1 = col[gl + 8];
            float2 x2 = col[gl + 16], x3 = col[gl + 24];
            float n2 = grp_sum(fmaf(x0.x, x0.x, x0.y * x0.y) +
                               fmaf(x1.x, x1.x, x1.y * x1.y) +
                               fmaf(x2.x, x2.x, x2.y * x2.y) +
                               fmaf(x3.x, x3.x, x3.y * x3.y));
            if (gl == 0) cn[k] = n2;
        }
        __syncthreads();

        // Incremental round-robin: p,q step +1 mod 63 (pair 0: p=63 fixed).
        int p = (pairid == 0) ? 63 : pairid;
        int q = (pairid == 0) ? 0  : 63 - pairid;

        for (int rr = 0; rr < 63; rr++) {
            float2* cp = Bs + p * LD2 + gl;
            float2* cq = Bs + q * LD2 + gl;
            float app = cn[p], aqq = cn[q];
            float2 bp0 = cp[0],  bq0 = cq[0];
            float2 bp1 = cp[8],  bq1 = cq[8];
            float2 bp2 = cp[16], bq2 = cq[16];
            float2 bp3 = cp[24], bq3 = cq[24];

            float apq = grp_sum(fmaf(bp0.x, bq0.x, bp0.y * bq0.y) +
                                fmaf(bp1.x, bq1.x, bp1.y * bq1.y) +
                                fmaf(bp2.x, bq2.x, bp2.y * bq2.y) +
                                fmaf(bp3.x, bq3.x, bp3.y * bq3.y));

            float a2 = apq * apq, pr = app * aqq;
            bool rot = a2 > RTOL * pr;              // uniform per group
            if (__any_sync(0xffffffffu, rot)) {
                float th = (aqq - app) / (2.0f * apq);
                float t  = copysignf(1.0f, th) / (fabsf(th) + sqrtf(1.0f + th * th));
                float c  = rsqrtf(1.0f + t * t);
                float s  = t * c;

                if (rot) {
                    cp[0]  = make_float2(c * bp0.x - s * bq0.x, c * bp0.y - s * bq0.y);
                    cp[8]  = make_float2(c * bp1.x - s * bq1.x, c * bp1.y - s * bq1.y);
                    cp[16] = make_float2(c * bp2.x - s * bq2.x, c * bp2.y - s * bq2.y);
                    cp[24] = make_float2(c * bp3.x - s * bq3.x, c * bp3.y - s * bq3.y);
                    cq[0]  = make_float2(s * bp0.x + c * bq0.x, s * bp0.y + c * bq0.y);
                    cq[8]  = make_float2(s * bp1.x + c * bq1.x, s * bp1.y + c * bq1.y);
                    cq[16] = make_float2(s * bp2.x + c * bq2.x, s * bp2.y + c * bq2.y);
                    cq[24] = make_float2(s * bp3.x + c * bq3.x, s * bp3.y + c * bq3.y);
                    if (gl == 0) {
                        cn[p] = app - t * apq;
                        cn[q] = aqq + t * apq;
                        if (a2 > QTOL * pr) nsig = 1;
                    }
                }
            }
            __syncthreads();

            if (pairid) { p++; if (p == 63) p = 0; }
            q++; if (q == 63) q = 0;
        }

        int s = nsig;
        __syncthreads();
        if (tid == 0) nsig = 0;
        __syncthreads();
        if (s == 0) break;
    }

    // ---- dv_k = log(l_k)/l_k^2 = 0.5*log(n2)/n2, n2 = l^2 ----
    #pragma unroll
    for (int h = 0; h < 2; h++) {
        int k = pairid + 32 * h;
        const float2* col = Bs + k * LD2;
        float2 x0 = col[gl],      x1 = col[gl + 8];
        float2 x2 = col[gl + 16], x3 = col[gl + 24];
        float n2 = grp_sum(fmaf(x0.x, x0.x, x0.y * x0.y) +
                           fmaf(x1.x, x1.x, x1.y * x1.y) +
                           fmaf(x2.x, x2.x, x2.y * x2.y) +
                           fmaf(x3.x, x3.x, x3.y * x3.y));
        if (gl == 0) dv[k] = 0.5f * logf(n2) / n2;
    }
    __syncthreads();

    // ---- out[i][j] = sum_k dv[k]*B[i,k]*B[j,k], i<=j.
    //      Warp w owns rows {8m+w paired with 63-(8m+w)}, m=0..3. ----
    #pragma unroll
    for (int rsel = 0; rsel < 8; rsel++) {
        int i = (rsel & 1) ? (63 - ((rsel >> 1) * 8 + warp))
                           : ((rsel >> 1) * 8 + warp);
        int base = i * (129 - i) / 2;
        for (int j = i + lane; j < MDIM; j += 32) {
            float acc = 0.0f;
            #pragma unroll
            for (int k = 0; k < MDIM; k++)
                acc += (dv[k] * Bf[k * LDF + i]) * Bf[k * LDF + j];
            O[base + (j - i)] = acc;
        }
    }
}

extern "C" void kernel_launch(void* const* d_in, const int* in_sizes, int n_in,
                              void* d_out, int out_size)
{
    const float* A = (const float*)d_in[0];
    float* out = (float*)d_out;
    int batch = in_sizes[0] / (MDIM * MDIM);   // 8192
    spd_log_kernel<<<batch, 256>>>(A, out);
}